// round 13
// baseline (speedup 1.0000x reference)
#include <cuda_runtime.h>

#define NN     256
#define NS     512
#define MAXSP  32
#define NSTEPS 32
#define VRESET 1.0f
#define JPT    2            // neurons per thread
#define NT     128          // threads per block
#define NWARP  (NT / 32)

__device__ __forceinline__ float sigmoidf_(float x) {
    float e = __expf(-x);
    return __fdividef(1.0f, 1.0f + e);
}

// monotonic float -> u32 key: a > b  <=>  fkey(a) > fkey(b)
__device__ __forceinline__ unsigned fkey(float f) {
    unsigned u = __float_as_uint(f);
    return ((int)u < 0) ? ~u : (u | 0x80000000u);
}

__global__ void __launch_bounds__(NT) snn_kernel(
    const float* __restrict__ input_current,  // [NN]
    const float* __restrict__ w,              // [NN, NN]
    const float* __restrict__ mu,             // [2]
    const float* __restrict__ v0,             // [NN]
    const float* __restrict__ i0,             // [NN]
    const float* __restrict__ s0,             // [NS, NN]
    const float* __restrict__ reset_s,        // [MAXSP, NS, NN]
    const int*   __restrict__ t1_raw,
    float* __restrict__ out_times,            // [NS, MAXSP]
    float* __restrict__ out_vals,             // [NS, MAXSP, NN, 3]
    float* __restrict__ out_marks)            // [NS, MAXSP, NN]
{
    const int s    = blockIdx.x;
    const int tid  = threadIdx.x;
    const int wid  = tid >> 5;
    const int lane = tid & 31;
    const unsigned FULL = 0xffffffffu;

    __shared__ uint4    red[NWARP];           // {key, bi, sp_bits, sn_bits}
    __shared__ unsigned ball[JPT * NWARP];

    // t1 dtype sniffing: small positive int -> integer payload; else float bits
    float t1f;
    {
        int iv = t1_raw[0];
        if (iv > 0 && iv < 1000000) t1f = (float)iv;
        else                        t1f = __int_as_float(iv);
    }

    const float m1 = mu[0];
    const float m2 = mu[1];

    // neuron indices: n_j = tid + j*NT (coalesced)
    float ic[JPT], yv[JPT], yi[JPT], ys[JPT];
    #pragma unroll
    for (int j = 0; j < JPT; ++j) {
        const int n = tid + j * NT;
        ic[j] = input_current[n];
        yv[j] = v0[n];
        yi[j] = i0[n];
        ys[j] = s0[s * NN + n];
    }
    float t0s = 0.0f;

    // software-pipelined reset_s: rs_cur holds round k's row
    float rs_cur[JPT], rs_nxt[JPT];
    #pragma unroll
    for (int j = 0; j < JPT; ++j)
        rs_cur[j] = __ldg(&reset_s[(long)s * NN + tid + j * NT]);   // k = 0

    for (int k = 0; k < MAXSP; ++k) {
        if (k + 1 < MAXSP) {
            #pragma unroll
            for (int j = 0; j < JPT; ++j)
                rs_nxt[j] = __ldg(&reset_s[((long)(k + 1) * NS + s) * NN + tid + j * NT]);
        }

        const float dt = (t1f - t0s) / (float)NSTEPS;
        const float h  = dt;
        const float hh = 0.5f * h;
        const float h6 = h / 6.0f;

        // ---- per-round affine RK4 coefficients (v,i are linear ODEs) ----
        const float i2c = 1.0f - hh * m2;
        const float i3c = 1.0f - hh * m2 * i2c;
        const float i4c = 1.0f - h  * m2 * i3c;
        const float Bi  = 1.0f - h6 * m2 * (1.0f + 2.0f * i2c + 2.0f * i3c + i4c);
        const float k1cv = -m1, k1ci = m1, k1cc = m1;
        const float v2cv = 1.0f + hh * k1cv, v2ci = hh * k1ci, v2cc = hh * k1cc;
        const float k2cv = -m1 * v2cv;
        const float k2ci = -m1 * v2ci + m1 * i2c;
        const float k2cc = -m1 * v2cc + m1;
        const float v3cv = 1.0f + hh * k2cv, v3ci = hh * k2ci, v3cc = hh * k2cc;
        const float k3cv = -m1 * v3cv;
        const float k3ci = -m1 * v3ci + m1 * i3c;
        const float k3cc = -m1 * v3cc + m1;
        const float v4cv = 1.0f + h * k3cv, v4ci = h * k3ci, v4cc = h * k3cc;
        const float k4cv = -m1 * v4cv;
        const float k4ci = -m1 * v4ci + m1 * i4c;
        const float k4cc = -m1 * v4cc + m1;
        const float Avv = 1.0f + h6 * (k1cv + 2.0f * k2cv + 2.0f * k3cv + k4cv);
        const float Avi =        h6 * (k1ci + 2.0f * k2ci + 2.0f * k3ci + k4ci);
        const float Avc =        h6 * (k1cc + 2.0f * k2cc + 2.0f * k3cc + k4cc);
        float v2K[JPT], v3K[JPT], v4K[JPT], nvK[JPT];
        #pragma unroll
        for (int j = 0; j < JPT; ++j) {
            v2K[j] = v2cc * ic[j];
            v3K[j] = v3cc * ic[j];
            v4K[j] = v4cc * ic[j];
            nvK[j] = Avc  * ic[j];
        }

        float tev  = t1f;
        bool  trig = false;
        int   emask = 0;       // bit j: neuron tid + j*NT crossed at event

        if (dt != 0.0f) {
            float t = t0s;
            for (int step = 0; step < NSTEPS; step += 2) {
                // ---- step A from y ----
                float avv[JPT], aii[JPT], ass[JPT];
                int anyA = 0;
                #pragma unroll
                for (int j = 0; j < JPT; ++j) {
                    const float v2 = fmaf(v2cv, yv[j], fmaf(v2ci, yi[j], v2K[j]));
                    const float v3 = fmaf(v3cv, yv[j], fmaf(v3ci, yi[j], v3K[j]));
                    const float v4 = fmaf(v4cv, yv[j], fmaf(v4ci, yi[j], v4K[j]));
                    const float s1 = sigmoidf_(yv[j]);
                    const float s2 = sigmoidf_(v2);
                    const float s3 = sigmoidf_(v3);
                    const float s4 = sigmoidf_(v4);
                    avv[j] = fmaf(Avv, yv[j], fmaf(Avi, yi[j], nvK[j]));
                    aii[j] = Bi * yi[j];
                    ass[j] = ys[j] + h6 * (s1 + 2.0f * s2 + 2.0f * s3 + s4);
                    anyA |= (ass[j] > 0.0f) ? 1 : 0;
                }
                // ---- step B from A (speculative) ----
                float bvv[JPT], bii[JPT], bss[JPT];
                int anyB = 0;
                #pragma unroll
                for (int j = 0; j < JPT; ++j) {
                    const float v2 = fmaf(v2cv, avv[j], fmaf(v2ci, aii[j], v2K[j]));
                    const float v3 = fmaf(v3cv, avv[j], fmaf(v3ci, aii[j], v3K[j]));
                    const float v4 = fmaf(v4cv, avv[j], fmaf(v4ci, aii[j], v4K[j]));
                    const float s1 = sigmoidf_(avv[j]);
                    const float s2 = sigmoidf_(v2);
                    const float s3 = sigmoidf_(v3);
                    const float s4 = sigmoidf_(v4);
                    bvv[j] = fmaf(Avv, avv[j], fmaf(Avi, aii[j], nvK[j]));
                    bii[j] = Bi * aii[j];
                    bss[j] = ass[j] + h6 * (s1 + 2.0f * s2 + 2.0f * s3 + s4);
                    anyB |= (bss[j] > 0.0f) ? 1 : 0;
                }

                // ONE barrier per 2 steps
                if (__syncthreads_or(anyA | anyB)) {
                    // which step fired first (block-wide)?
                    const bool trigA = __syncthreads_or(anyA) != 0;
                    // event-step (prev, new) per neuron
                    float pv[JPT], pi_[JPT], ps[JPT], qv[JPT], qi[JPT], qs[JPT];
                    #pragma unroll
                    for (int j = 0; j < JPT; ++j) {
                        pv[j] = trigA ? yv[j]  : avv[j];
                        pi_[j]= trigA ? yi[j]  : aii[j];
                        ps[j] = trigA ? ys[j]  : ass[j];
                        qv[j] = trigA ? avv[j] : bvv[j];
                        qi[j] = trigA ? aii[j] : bii[j];
                        qs[j] = trigA ? ass[j] : bss[j];
                    }
                    const float tbase = trigA ? t : (t + dt);

                    // crossed ballots (feed eidx scan post-barrier)
                    unsigned em0 = __ballot_sync(FULL, qs[0] > 0.0f);
                    unsigned em1 = __ballot_sync(FULL, qs[1] > 0.0f);
                    if (lane == 0) { ball[wid] = em0; ball[NWARP + wid] = em1; }

                    // L1 prefetch of this warp's first-crossed row
                    int cand = -1;
                    if (em0)      cand = wid * 32 + __ffs(em0) - 1;
                    else if (em1) cand = NT + wid * 32 + __ffs(em1) - 1;
                    if (cand >= 0 && lane < 8)
                        asm volatile("prefetch.global.L1 [%0];"
                                     :: "l"(&w[cand * NN + lane * 32]));

                    // ---- exact argmax via REDUX on monotonic key ----
                    const unsigned key0 = fkey(qs[0]);
                    const unsigned key1 = fkey(qs[1]);
                    unsigned kb; int bj;
                    if (key1 > key0) { kb = key1; bj = 1; }
                    else             { kb = key0; bj = 0; }
                    const unsigned wmax = __reduce_max_sync(FULL, kb);
                    unsigned b0 = __ballot_sync(FULL, (kb == wmax) && (bj == 0));
                    int wlane, wbi;
                    if (b0) { wlane = __ffs(b0) - 1; wbi = wid * 32 + wlane; }
                    else {
                        unsigned b1 = __ballot_sync(FULL, kb == wmax);
                        wlane = __ffs(b1) - 1; wbi = NT + wid * 32 + wlane;
                    }
                    if (lane == wlane) {
                        const float sp_ = (wbi < NT) ? ps[0] : ps[JPT - 1];
                        const float sn_ = (wbi < NT) ? qs[0] : qs[JPT - 1];
                        red[wid] = make_uint4(wmax, (unsigned)wbi,
                                              __float_as_uint(sp_),
                                              __float_as_uint(sn_));
                    }
                    __syncthreads();

                    uint4 best = red[0];
                    #pragma unroll
                    for (int ww = 1; ww < NWARP; ++ww) {
                        uint4 c = red[ww];
                        if (c.x > best.x || (c.x == best.x && c.y < best.y)) best = c;
                    }
                    const float sp = __uint_as_float(best.z);
                    const float sn = __uint_as_float(best.w);
                    float frac = sp / (sp - sn + 1e-12f);
                    frac = fminf(fmaxf(frac, 0.0f), 1.0f);
                    tev = tbase + frac * dt;
                    #pragma unroll
                    for (int j = 0; j < JPT; ++j) {
                        yv[j] = pv[j]  + frac * (qv[j] - pv[j]);
                        yi[j] = pi_[j] + frac * (qi[j] - pi_[j]);
                        ys[j] = ps[j]  + frac * (qs[j] - ps[j]);
                        if (qs[j] > 0.0f) emask |= (1 << j);
                    }
                    trig = true;
                    break;
                }
                #pragma unroll
                for (int j = 0; j < JPT; ++j) { yv[j] = bvv[j]; yi[j] = bii[j]; ys[j] = bss[j]; }
                t += 2.0f * dt;
            }
        }

        // ---- outputs (event state = current y) ----
        if (tid == 0) out_times[s * MAXSP + k] = tev;
        const long row = (long)(s * MAXSP + k);
        #pragma unroll
        for (int j = 0; j < JPT; ++j) {
            const int n = tid + j * NT;
            const long base = (row * NN + n) * 3;
            out_vals[base + 0] = yv[j];
            out_vals[base + 1] = yi[j];
            out_vals[base + 2] = ys[j];
            out_marks[row * NN + n] = (emask >> j) & 1 ? 1.0f : 0.0f;
        }

        // ---- next-round state ----
        if (trig) {
            int eidx = 0;
            #pragma unroll
            for (int q = 0; q < JPT * NWARP; ++q) {
                unsigned bb = ball[q];
                if (bb) { eidx = (q / NWARP) * NT + (q % NWARP) * 32 + __ffs(bb) - 1; break; }
            }
            #pragma unroll
            for (int j = 0; j < JPT; ++j) {
                const int n = tid + j * NT;
                const bool em = (emask >> j) & 1;
                yv[j] = yv[j] - (em ? VRESET : 0.0f);
                yi[j] = yi[j] + w[eidx * NN + n];       // L1 hit via prefetch
                ys[j] = fminf(em ? rs_cur[j] : ys[j], 0.0f);
            }
        } else {
            #pragma unroll
            for (int j = 0; j < JPT; ++j) ys[j] = fminf(ys[j], 0.0f);
        }
        t0s = tev;
        #pragma unroll
        for (int j = 0; j < JPT; ++j) rs_cur[j] = rs_nxt[j];
        // no trailing barrier: next round's first __syncthreads_or orders smem reuse
    }
}

extern "C" void kernel_launch(void* const* d_in, const int* in_sizes, int n_in,
                              void* d_out, int out_size) {
    const float* input_current = (const float*)d_in[0];
    const float* w             = (const float*)d_in[1];
    const float* mu            = (const float*)d_in[2];
    const float* v0            = (const float*)d_in[3];
    const float* i0            = (const float*)d_in[4];
    const float* s0            = (const float*)d_in[5];
    const float* reset_s       = (const float*)d_in[6];
    const int*   t1            = (const int*)  d_in[7];

    float* out = (float*)d_out;
    float* out_times = out;                                      // 512*32
    float* out_vals  = out + (long)NS * MAXSP;                   // 512*32*256*3
    float* out_marks = out + (long)NS * MAXSP
                           + (long)NS * MAXSP * NN * 3;          // 512*32*256

    snn_kernel<<<NS, NT>>>(input_current, w, mu, v0, i0, s0, reset_s, t1,
                           out_times, out_vals, out_marks);
}

// round 14
// speedup vs baseline: 1.0734x; 1.0734x over previous
#include <cuda_runtime.h>

#define NN     256
#define NS     512
#define MAXSP  32
#define NSTEPS 32
#define VRESET 1.0f
#define JPT    2            // neurons per thread
#define NT     128          // threads per block
#define NWARP  (NT / 32)

__device__ __forceinline__ float sigmoidf_(float x) {
    float e = __expf(-x);
    return __fdividef(1.0f, 1.0f + e);
}

// monotonic float -> u32 key: a > b  <=>  fkey(a) > fkey(b)
__device__ __forceinline__ unsigned fkey(float f) {
    unsigned u = __float_as_uint(f);
    return ((int)u < 0) ? ~u : (u | 0x80000000u);
}

__global__ void __launch_bounds__(NT) snn_kernel(
    const float* __restrict__ input_current,  // [NN]
    const float* __restrict__ w,              // [NN, NN]
    const float* __restrict__ mu,             // [2]
    const float* __restrict__ v0,             // [NN]
    const float* __restrict__ i0,             // [NN]
    const float* __restrict__ s0,             // [NS, NN]
    const float* __restrict__ reset_s,        // [MAXSP, NS, NN]
    const int*   __restrict__ t1_raw,
    float* __restrict__ out_times,            // [NS, MAXSP]
    float* __restrict__ out_vals,             // [NS, MAXSP, NN, 3]
    float* __restrict__ out_marks)            // [NS, MAXSP, NN]
{
    const int s    = blockIdx.x;
    const int tid  = threadIdx.x;
    const int wid  = tid >> 5;
    const int lane = tid & 31;
    const unsigned FULL = 0xffffffffu;

    // round-parity double-buffered publish area (written pre-barrier on the
    // trigger step, read post-barrier; parity prevents cross-round races)
    __shared__ uint4    red[2][NWARP];        // {key, bi, sp_bits, sn_bits}
    __shared__ int      stamp[2][NWARP];      // cnt of publishing step
    __shared__ unsigned ball[2][JPT * NWARP];

    if (tid < 2 * NWARP) stamp[tid / NWARP][tid % NWARP] = -1;
    // (visibility guaranteed by the first __syncthreads_or before any read)

    // t1 dtype sniffing: small positive int -> integer payload; else float bits
    float t1f;
    {
        int iv = t1_raw[0];
        if (iv > 0 && iv < 1000000) t1f = (float)iv;
        else                        t1f = __int_as_float(iv);
    }

    const float m1 = mu[0];
    const float m2 = mu[1];

    // neuron indices: n_j = tid + j*NT (coalesced)
    float ic[JPT], yv[JPT], yi[JPT], ys[JPT];
    #pragma unroll
    for (int j = 0; j < JPT; ++j) {
        const int n = tid + j * NT;
        ic[j] = input_current[n];
        yv[j] = v0[n];
        yi[j] = i0[n];
        ys[j] = s0[s * NN + n];
    }
    float t0s = 0.0f;
    int   cnt = 0;                 // uniform step counter (stamps)

    // software-pipelined reset_s: rs_cur holds round k's row
    float rs_cur[JPT], rs_nxt[JPT];
    #pragma unroll
    for (int j = 0; j < JPT; ++j)
        rs_cur[j] = __ldg(&reset_s[(long)s * NN + tid + j * NT]);   // k = 0

    for (int k = 0; k < MAXSP; ++k) {
        const int par = k & 1;
        if (k + 1 < MAXSP) {
            #pragma unroll
            for (int j = 0; j < JPT; ++j)
                rs_nxt[j] = __ldg(&reset_s[((long)(k + 1) * NS + s) * NN + tid + j * NT]);
        }

        const float dt = (t1f - t0s) * 0.03125f;   // /32, exact
        const float h  = dt;
        const float hh = 0.5f * h;
        const float h6 = h / 6.0f;

        // ---- per-round affine RK4 coefficients (v,i are linear ODEs) ----
        const float i2c = 1.0f - hh * m2;
        const float i3c = 1.0f - hh * m2 * i2c;
        const float i4c = 1.0f - h  * m2 * i3c;
        const float Bi  = 1.0f - h6 * m2 * (1.0f + 2.0f * i2c + 2.0f * i3c + i4c);
        const float k1cv = -m1, k1ci = m1, k1cc = m1;
        const float v2cv = 1.0f + hh * k1cv, v2ci = hh * k1ci, v2cc = hh * k1cc;
        const float k2cv = -m1 * v2cv;
        const float k2ci = -m1 * v2ci + m1 * i2c;
        const float k2cc = -m1 * v2cc + m1;
        const float v3cv = 1.0f + hh * k2cv, v3ci = hh * k2ci, v3cc = hh * k2cc;
        const float k3cv = -m1 * v3cv;
        const float k3ci = -m1 * v3ci + m1 * i3c;
        const float k3cc = -m1 * v3cc + m1;
        const float v4cv = 1.0f + h * k3cv, v4ci = h * k3ci, v4cc = h * k3cc;
        const float k4cv = -m1 * v4cv;
        const float k4ci = -m1 * v4ci + m1 * i4c;
        const float k4cc = -m1 * v4cc + m1;
        const float Avv = 1.0f + h6 * (k1cv + 2.0f * k2cv + 2.0f * k3cv + k4cv);
        const float Avi =        h6 * (k1ci + 2.0f * k2ci + 2.0f * k3ci + k4ci);
        const float Avc =        h6 * (k1cc + 2.0f * k2cc + 2.0f * k3cc + k4cc);
        // Simpson midpoint coefficients: v23 = (v2+v3)/2 as direct affine map
        const float v23cv = 0.5f * (v2cv + v3cv);
        const float v23ci = 0.5f * (v2ci + v3ci);
        const float v23cc = 0.5f * (v2cc + v3cc);
        float v2K[JPT], v23K[JPT], v4K[JPT], nvK[JPT];
        #pragma unroll
        for (int j = 0; j < JPT; ++j) {
            v2K[j]  = v2cc  * ic[j];
            v23K[j] = v23cc * ic[j];
            v4K[j]  = v4cc  * ic[j];
            nvK[j]  = Avc   * ic[j];
        }

        float tev  = t1f;
        bool  trig = false;
        int   emask = 0;       // bit j: neuron tid + j*NT crossed at event

        if (dt != 0.0f) {
            float t = t0s;
            for (int step = 0; step < NSTEPS; ++step) {
                ++cnt;
                float nv[JPT], ni[JPT], ns[JPT];
                #pragma unroll
                for (int j = 0; j < JPT; ++j) {
                    // ---- affine RK4 step, Simpson 3-sigmoid quadrature ----
                    const float v2  = fmaf(v2cv,  yv[j], fmaf(v2ci,  yi[j], v2K[j]));
                    const float v23 = fmaf(v23cv, yv[j], fmaf(v23ci, yi[j], v23K[j]));
                    const float v4  = fmaf(v4cv,  yv[j], fmaf(v4ci,  yi[j], v4K[j]));
                    const float s1  = sigmoidf_(yv[j]);
                    const float s23 = sigmoidf_(v23);
                    const float s4  = sigmoidf_(v4);
                    nv[j] = fmaf(Avv, yv[j], fmaf(Avi, yi[j], nvK[j]));
                    ni[j] = Bi * yi[j];
                    ns[j] = fmaf(h6, fmaf(4.0f, s23, s1 + s4), ys[j]);
                }

                // crossing ballots (cheap, every step)
                const unsigned em0 = __ballot_sync(FULL, ns[0] > 0.0f);
                const unsigned em1 = __ballot_sync(FULL, ns[1] > 0.0f);

                // crossing warps publish ballots + argmax tuple BEFORE the OR
                // barrier (the block argmax is always in a crossing warp)
                if (em0 | em1) {
                    if (lane == 0) {
                        ball[par][wid] = em0;
                        ball[par][NWARP + wid] = em1;
                        stamp[par][wid] = cnt;
                    }
                    // L1 prefetch of this warp's first-crossed row
                    int cand = em0 ? (wid * 32 + __ffs(em0) - 1)
                                   : (NT + wid * 32 + __ffs(em1) - 1);
                    if (lane < 8)
                        asm volatile("prefetch.global.L1 [%0];"
                                     :: "l"(&w[cand * NN + lane * 32]));
                    // exact warp argmax via REDUX on monotonic key
                    const unsigned key0 = fkey(ns[0]);
                    const unsigned key1 = fkey(ns[1]);
                    unsigned kb; int bj;
                    if (key1 > key0) { kb = key1; bj = 1; }
                    else             { kb = key0; bj = 0; }
                    const unsigned wmax = __reduce_max_sync(FULL, kb);
                    unsigned b0 = __ballot_sync(FULL, (kb == wmax) && (bj == 0));
                    int wlane, wbi;
                    if (b0) { wlane = __ffs(b0) - 1; wbi = wid * 32 + wlane; }
                    else {
                        unsigned b1 = __ballot_sync(FULL, kb == wmax);
                        wlane = __ffs(b1) - 1; wbi = NT + wid * 32 + wlane;
                    }
                    if (lane == wlane) {
                        const float sp_ = (wbi < NT) ? ys[0] : ys[JPT - 1];
                        const float sn_ = (wbi < NT) ? ns[0] : ns[JPT - 1];
                        red[par][wid] = make_uint4(wmax, (unsigned)wbi,
                                                   __float_as_uint(sp_),
                                                   __float_as_uint(sn_));
                    }
                }

                // single barrier per step
                if (__syncthreads_or((em0 | em1) != 0)) {
                    // combine stamped tuples (at least one exists)
                    uint4 best; bool have = false;
                    #pragma unroll
                    for (int ww = 0; ww < NWARP; ++ww) {
                        if (stamp[par][ww] == cnt) {
                            uint4 c = red[par][ww];
                            if (!have || c.x > best.x ||
                                (c.x == best.x && c.y < best.y)) { best = c; have = true; }
                        }
                    }
                    const float sp = __uint_as_float(best.z);
                    const float sn = __uint_as_float(best.w);
                    float frac = sp / (sp - sn + 1e-12f);
                    frac = fminf(fmaxf(frac, 0.0f), 1.0f);
                    tev = t + frac * dt;
                    #pragma unroll
                    for (int j = 0; j < JPT; ++j) {
                        yv[j] = yv[j] + frac * (nv[j] - yv[j]);
                        yi[j] = yi[j] + frac * (ni[j] - yi[j]);
                        ys[j] = ys[j] + frac * (ns[j] - ys[j]);
                        if (ns[j] > 0.0f) emask |= (1 << j);
                    }
                    trig = true;
                    break;
                }
                #pragma unroll
                for (int j = 0; j < JPT; ++j) { yv[j] = nv[j]; yi[j] = ni[j]; ys[j] = ns[j]; }
                t += dt;
            }
        }

        // ---- outputs (event state = current y) ----
        if (tid == 0) out_times[s * MAXSP + k] = tev;
        const long row = (long)(s * MAXSP + k);
        #pragma unroll
        for (int j = 0; j < JPT; ++j) {
            const int n = tid + j * NT;
            const long base = (row * NN + n) * 3;
            out_vals[base + 0] = yv[j];
            out_vals[base + 1] = yi[j];
            out_vals[base + 2] = ys[j];
            out_marks[row * NN + n] = (emask >> j) & 1 ? 1.0f : 0.0f;
        }

        // ---- next-round state ----
        if (trig) {
            // eidx = first neuron index with event mark (stamped ballots)
            int eidx = 0;
            #pragma unroll
            for (int q = 0; q < JPT * NWARP; ++q) {
                const int ww = q % NWARP;
                unsigned bb = (stamp[par][ww] == cnt) ? ball[par][q] : 0u;
                if (bb) { eidx = (q / NWARP) * NT + ww * 32 + __ffs(bb) - 1; break; }
            }
            #pragma unroll
            for (int j = 0; j < JPT; ++j) {
                const int n = tid + j * NT;
                const bool em = (emask >> j) & 1;
                yv[j] = yv[j] - (em ? VRESET : 0.0f);
                yi[j] = yi[j] + w[eidx * NN + n];       // L1 hit via prefetch
                ys[j] = fminf(em ? rs_cur[j] : ys[j], 0.0f);
            }
        } else {
            #pragma unroll
            for (int j = 0; j < JPT; ++j) ys[j] = fminf(ys[j], 0.0f);
        }
        t0s = tev;
        #pragma unroll
        for (int j = 0; j < JPT; ++j) rs_cur[j] = rs_nxt[j];
        // no trailing barrier: parity double-buffering + stamps make the next
        // round's pre-barrier publishes race-free against this round's reads
    }
}

extern "C" void kernel_launch(void* const* d_in, const int* in_sizes, int n_in,
                              void* d_out, int out_size) {
    const float* input_current = (const float*)d_in[0];
    const float* w             = (const float*)d_in[1];
    const float* mu            = (const float*)d_in[2];
    const float* v0            = (const float*)d_in[3];
    const float* i0            = (const float*)d_in[4];
    const float* s0            = (const float*)d_in[5];
    const float* reset_s       = (const float*)d_in[6];
    const int*   t1            = (const int*)  d_in[7];

    float* out = (float*)d_out;
    float* out_times = out;                                      // 512*32
    float* out_vals  = out + (long)NS * MAXSP;                   // 512*32*256*3
    float* out_marks = out + (long)NS * MAXSP
                           + (long)NS * MAXSP * NN * 3;          // 512*32*256

    snn_kernel<<<NS, NT>>>(input_current, w, mu, v0, i0, s0, reset_s, t1,
                           out_times, out_vals, out_marks);
}

// round 15
// speedup vs baseline: 1.1852x; 1.1042x over previous
#include <cuda_runtime.h>

#define NN     256
#define NS     512
#define MAXSP  32
#define NSTEPS 32
#define VRESET 1.0f
#define JPT    2            // neurons per thread
#define NT     128          // threads per block
#define NWARP  (NT / 32)

__device__ __forceinline__ float sigmoidf_(float x) {
    float e = __expf(-x);
    return __fdividef(1.0f, 1.0f + e);
}

// monotonic float -> u32 key: a > b  <=>  fkey(a) > fkey(b)
__device__ __forceinline__ unsigned fkey(float f) {
    unsigned u = __float_as_uint(f);
    return ((int)u < 0) ? ~u : (u | 0x80000000u);
}

__global__ void __launch_bounds__(NT) snn_kernel(
    const float* __restrict__ input_current,  // [NN]
    const float* __restrict__ w,              // [NN, NN]
    const float* __restrict__ mu,             // [2]
    const float* __restrict__ v0,             // [NN]
    const float* __restrict__ i0,             // [NN]
    const float* __restrict__ s0,             // [NS, NN]
    const float* __restrict__ reset_s,        // [MAXSP, NS, NN]
    const int*   __restrict__ t1_raw,
    float* __restrict__ out_times,            // [NS, MAXSP]
    float* __restrict__ out_vals,             // [NS, MAXSP, NN, 3]
    float* __restrict__ out_marks)            // [NS, MAXSP, NN]
{
    const int s    = blockIdx.x;
    const int tid  = threadIdx.x;
    const int wid  = tid >> 5;
    const int lane = tid & 31;
    const unsigned FULL = 0xffffffffu;

    __shared__ uint4    red[NWARP];           // {key, bi, sp_bits, sn_bits}
    __shared__ unsigned ball[JPT * NWARP];

    // t1 dtype sniffing: small positive int -> integer payload; else float bits
    float t1f;
    {
        int iv = t1_raw[0];
        if (iv > 0 && iv < 1000000) t1f = (float)iv;
        else                        t1f = __int_as_float(iv);
    }

    const float m1 = mu[0];
    const float m2 = mu[1];

    // neuron indices: n_j = tid + j*NT (coalesced)
    float ic[JPT], yv[JPT], yi[JPT], ys[JPT];
    #pragma unroll
    for (int j = 0; j < JPT; ++j) {
        const int n = tid + j * NT;
        ic[j] = input_current[n];
        yv[j] = v0[n];
        yi[j] = i0[n];
        ys[j] = s0[s * NN + n];
    }
    float t0s = 0.0f;

    // software-pipelined reset_s: rs_cur holds round k's row
    float rs_cur[JPT], rs_nxt[JPT];
    #pragma unroll
    for (int j = 0; j < JPT; ++j)
        rs_cur[j] = __ldg(&reset_s[(long)s * NN + tid + j * NT]);   // k = 0

    for (int k = 0; k < MAXSP; ++k) {
        if (k + 1 < MAXSP) {
            #pragma unroll
            for (int j = 0; j < JPT; ++j)
                rs_nxt[j] = __ldg(&reset_s[((long)(k + 1) * NS + s) * NN + tid + j * NT]);
        }

        const float dt = (t1f - t0s) * 0.03125f;   // /32, exact (power of two)
        const float h  = dt;
        const float hh = 0.5f * h;
        const float h6 = h / 6.0f;

        // ---- per-round affine RK4 coefficients (v,i are linear ODEs) ----
        const float i2c = 1.0f - hh * m2;
        const float i3c = 1.0f - hh * m2 * i2c;
        const float i4c = 1.0f - h  * m2 * i3c;
        const float Bi  = 1.0f - h6 * m2 * (1.0f + 2.0f * i2c + 2.0f * i3c + i4c);
        const float k1cv = -m1, k1ci = m1, k1cc = m1;
        const float v2cv = 1.0f + hh * k1cv, v2ci = hh * k1ci, v2cc = hh * k1cc;
        const float k2cv = -m1 * v2cv;
        const float k2ci = -m1 * v2ci + m1 * i2c;
        const float k2cc = -m1 * v2cc + m1;
        const float v3cv = 1.0f + hh * k2cv, v3ci = hh * k2ci, v3cc = hh * k2cc;
        const float k3cv = -m1 * v3cv;
        const float k3ci = -m1 * v3ci + m1 * i3c;
        const float k3cc = -m1 * v3cc + m1;
        const float v4cv = 1.0f + h * k3cv, v4ci = h * k3ci, v4cc = h * k3cc;
        const float k4cv = -m1 * v4cv;
        const float k4ci = -m1 * v4ci + m1 * i4c;
        const float k4cc = -m1 * v4cc + m1;
        const float Avv = 1.0f + h6 * (k1cv + 2.0f * k2cv + 2.0f * k3cv + k4cv);
        const float Avi =        h6 * (k1ci + 2.0f * k2ci + 2.0f * k3ci + k4ci);
        const float Avc =        h6 * (k1cc + 2.0f * k2cc + 2.0f * k3cc + k4cc);
        // Simpson midpoint: v23 = (v2+v3)/2 as a direct affine map
        const float v23cv = 0.5f * (v2cv + v3cv);
        const float v23ci = 0.5f * (v2ci + v3ci);
        const float v23cc = 0.5f * (v2cc + v3cc);
        float v23K[JPT], v4K[JPT], nvK[JPT];
        #pragma unroll
        for (int j = 0; j < JPT; ++j) {
            v23K[j] = v23cc * ic[j];
            v4K[j]  = v4cc  * ic[j];
            nvK[j]  = Avc   * ic[j];
        }

        float tev  = t1f;
        bool  trig = false;
        int   emask = 0;       // bit j: neuron tid + j*NT crossed at event

        if (dt != 0.0f) {
            float t = t0s;
            for (int step = 0; step < NSTEPS; ++step) {
                float nv[JPT], ni[JPT], ns[JPT];
                #pragma unroll
                for (int j = 0; j < JPT; ++j) {
                    // ---- affine RK4 step, Simpson 3-sigmoid quadrature ----
                    const float v23 = fmaf(v23cv, yv[j], fmaf(v23ci, yi[j], v23K[j]));
                    const float v4  = fmaf(v4cv,  yv[j], fmaf(v4ci,  yi[j], v4K[j]));
                    const float s1  = sigmoidf_(yv[j]);
                    const float s23 = sigmoidf_(v23);
                    const float s4  = sigmoidf_(v4);
                    nv[j] = fmaf(Avv, yv[j], fmaf(Avi, yi[j], nvK[j]));
                    ni[j] = Bi * yi[j];
                    ns[j] = fmaf(h6, fmaf(4.0f, s23, s1 + s4), ys[j]);
                }

                // single hardware BAR.RED per step — trigger fast path
                if (__syncthreads_or(fmaxf(ns[0], ns[1]) > 0.0f)) {
                    // ---- crossed ballots (feed eidx scan post-barrier) ----
                    unsigned em0 = __ballot_sync(FULL, ns[0] > 0.0f);
                    unsigned em1 = __ballot_sync(FULL, ns[1] > 0.0f);
                    if (lane == 0) { ball[wid] = em0; ball[NWARP + wid] = em1; }

                    // L1 prefetch of this warp's first-crossed row
                    int cand = -1;
                    if (em0)      cand = wid * 32 + __ffs(em0) - 1;
                    else if (em1) cand = NT + wid * 32 + __ffs(em1) - 1;
                    if (cand >= 0 && lane < 8)
                        asm volatile("prefetch.global.L1 [%0];"
                                     :: "l"(&w[cand * NN + lane * 32]));

                    // ---- exact argmax via REDUX on monotonic key ----
                    const unsigned key0 = fkey(ns[0]);
                    const unsigned key1 = fkey(ns[1]);
                    unsigned kb; int bj;
                    if (key1 > key0) { kb = key1; bj = 1; }
                    else             { kb = key0; bj = 0; }
                    const unsigned wmax = __reduce_max_sync(FULL, kb);
                    unsigned b0 = __ballot_sync(FULL, (kb == wmax) && (bj == 0));
                    int wlane, wbi;
                    if (b0) { wlane = __ffs(b0) - 1; wbi = wid * 32 + wlane; }
                    else {
                        unsigned b1 = __ballot_sync(FULL, kb == wmax);
                        wlane = __ffs(b1) - 1; wbi = NT + wid * 32 + wlane;
                    }
                    if (lane == wlane) {
                        const float sp_ = (wbi < NT) ? ys[0] : ys[JPT - 1];
                        const float sn_ = (wbi < NT) ? ns[0] : ns[JPT - 1];
                        red[wid] = make_uint4(wmax, (unsigned)wbi,
                                              __float_as_uint(sp_),
                                              __float_as_uint(sn_));
                    }
                    __syncthreads();

                    uint4 best = red[0];
                    #pragma unroll
                    for (int ww = 1; ww < NWARP; ++ww) {
                        uint4 c = red[ww];
                        if (c.x > best.x || (c.x == best.x && c.y < best.y)) best = c;
                    }
                    const float sp = __uint_as_float(best.z);
                    const float sn = __uint_as_float(best.w);
                    float frac = sp / (sp - sn + 1e-12f);
                    frac = fminf(fmaxf(frac, 0.0f), 1.0f);
                    tev = t + frac * dt;
                    #pragma unroll
                    for (int j = 0; j < JPT; ++j) {
                        yv[j] = yv[j] + frac * (nv[j] - yv[j]);
                        yi[j] = yi[j] + frac * (ni[j] - yi[j]);
                        ys[j] = ys[j] + frac * (ns[j] - ys[j]);
                        if (ns[j] > 0.0f) emask |= (1 << j);
                    }
                    trig = true;
                    break;
                }
                #pragma unroll
                for (int j = 0; j < JPT; ++j) { yv[j] = nv[j]; yi[j] = ni[j]; ys[j] = ns[j]; }
                t += dt;
            }
        }

        // ---- outputs (event state = current y) ----
        if (tid == 0) out_times[s * MAXSP + k] = tev;
        const long row = (long)(s * MAXSP + k);
        #pragma unroll
        for (int j = 0; j < JPT; ++j) {
            const int n = tid + j * NT;
            const long base = (row * NN + n) * 3;
            out_vals[base + 0] = yv[j];
            out_vals[base + 1] = yi[j];
            out_vals[base + 2] = ys[j];
            out_marks[row * NN + n] = (emask >> j) & 1 ? 1.0f : 0.0f;
        }

        // ---- next-round state ----
        if (trig) {
            // eidx = first neuron index with event mark (ball[] written pre-barrier)
            int eidx = 0;
            #pragma unroll
            for (int q = 0; q < JPT * NWARP; ++q) {
                unsigned bb = ball[q];
                if (bb) { eidx = (q / NWARP) * NT + (q % NWARP) * 32 + __ffs(bb) - 1; break; }
            }
            #pragma unroll
            for (int j = 0; j < JPT; ++j) {
                const int n = tid + j * NT;
                const bool em = (emask >> j) & 1;
                yv[j] = yv[j] - (em ? VRESET : 0.0f);
                yi[j] = yi[j] + w[eidx * NN + n];       // L1 hit via prefetch
                ys[j] = fminf(em ? rs_cur[j] : ys[j], 0.0f);
            }
        } else {
            #pragma unroll
            for (int j = 0; j < JPT; ++j) ys[j] = fminf(ys[j], 0.0f);
        }
        t0s = tev;
        #pragma unroll
        for (int j = 0; j < JPT; ++j) rs_cur[j] = rs_nxt[j];
        // no trailing barrier: next round's first __syncthreads_or orders smem reuse
    }
}

extern "C" void kernel_launch(void* const* d_in, const int* in_sizes, int n_in,
                              void* d_out, int out_size) {
    const float* input_current = (const float*)d_in[0];
    const float* w             = (const float*)d_in[1];
    const float* mu            = (const float*)d_in[2];
    const float* v0            = (const float*)d_in[3];
    const float* i0            = (const float*)d_in[4];
    const float* s0            = (const float*)d_in[5];
    const float* reset_s       = (const float*)d_in[6];
    const int*   t1            = (const int*)  d_in[7];

    float* out = (float*)d_out;
    float* out_times = out;                                      // 512*32
    float* out_vals  = out + (long)NS * MAXSP;                   // 512*32*256*3
    float* out_marks = out + (long)NS * MAXSP
                           + (long)NS * MAXSP * NN * 3;          // 512*32*256

    snn_kernel<<<NS, NT>>>(input_current, w, mu, v0, i0, s0, reset_s, t1,
                           out_times, out_vals, out_marks);
}